// round 5
// baseline (speedup 1.0000x reference)
#include <cuda_runtime.h>
#include <cuda_bf16.h>
#include <cstdint>

#define BATCH 32
#define C 512
#define HW 3136
#define HID 128
#define PIX_TILE 128
#define TILES 25
#define PITCH 136           // bf16 pitch for 128-wide tiles (272B rows)
#define PITCHW 72           // bf16 pitch for 64-wide W1 chunks (144B rows)
#define PITCHF 132          // fp32 pitch for X staging
#define EPS_BN 1e-5f

// ---- smem map (bf16 elements unless noted) ----
// [0, 34816)            sH hi/lo            : 2 * 128*136
// Phase A (aliased with Phase B below):
//   [34816, 71680)      W1 double buffer    : 2 bufs * (hi 128*72 + lo 128*72)
//   [71680, 89088)      sX hi/lo            : 2 * 64*136
//   [89088, +16896)     fp32 stage (8448 floats = 16896 bf16-slots)
// Phase B:
//   [34816, 104448)     W2 double buffer    : 2 bufs * (hi 128*136 + lo 128*136)
#define SMEM_BYTES ((89088 + 16896) * 2)   // 211968 B

__device__ __align__(16) __nv_bfloat16 g_w1h[2*HID*C];
__device__ __align__(16) __nv_bfloat16 g_w1l[2*HID*C];
__device__ __align__(16) __nv_bfloat16 g_w2h[2*C*HID];
__device__ __align__(16) __nv_bfloat16 g_w2l[2*C*HID];
__device__ float g_ss[2*2*HID];

__device__ __forceinline__ void split_bf16(float v, __nv_bfloat16& h, __nv_bfloat16& l) {
    h = __float2bfloat16(v);
    l = __float2bfloat16(v - __bfloat162float(h));
}

__global__ void prep_kernel(const float* __restrict__ w1r, const float* __restrict__ w1i,
                            const float* __restrict__ w2r, const float* __restrict__ w2i,
                            const float* __restrict__ rmr, const float* __restrict__ rvr,
                            const float* __restrict__ gr,  const float* __restrict__ bbr,
                            const float* __restrict__ rmi, const float* __restrict__ rvi,
                            const float* __restrict__ gi,  const float* __restrict__ bbi)
{
    int idx = blockIdx.x * blockDim.x + threadIdx.x;
    if (idx < HID * C) {
        split_bf16(w1r[idx], g_w1h[idx],         g_w1l[idx]);
        split_bf16(w1i[idx], g_w1h[HID*C + idx], g_w1l[HID*C + idx]);
        split_bf16(w2r[idx], g_w2h[idx],         g_w2l[idx]);
        split_bf16(w2i[idx], g_w2h[C*HID + idx], g_w2l[C*HID + idx]);
    }
    if (idx < HID) {
        float s0 = gr[idx] / sqrtf(rvr[idx] + EPS_BN);
        g_ss[idx]         = s0;
        g_ss[HID + idx]   = bbr[idx] - rmr[idx] * s0;
        float s1 = gi[idx] / sqrtf(rvi[idx] + EPS_BN);
        g_ss[2*HID + idx] = s1;
        g_ss[3*HID + idx] = bbi[idx] - rmi[idx] * s1;
    }
}

__device__ __forceinline__ void cp16(const void* dst_smem, const void* src) {
    uint32_t d = (uint32_t)__cvta_generic_to_shared(dst_smem);
    asm volatile("cp.async.cg.shared.global [%0], [%1], 16;\n" :: "r"(d), "l"(src));
}
#define CP_COMMIT() asm volatile("cp.async.commit_group;\n" ::)
#define CP_WAIT0()  asm volatile("cp.async.wait_group 0;\n" ::)

__device__ __forceinline__ void ldsm4(uint32_t r[4], const __nv_bfloat16* p) {
    uint32_t a = (uint32_t)__cvta_generic_to_shared(p);
    asm volatile("ldmatrix.sync.aligned.m8n8.x4.shared.b16 {%0,%1,%2,%3}, [%4];"
                 : "=r"(r[0]), "=r"(r[1]), "=r"(r[2]), "=r"(r[3]) : "r"(a));
}
__device__ __forceinline__ void ldsm4t(uint32_t r[4], const __nv_bfloat16* p) {
    uint32_t a = (uint32_t)__cvta_generic_to_shared(p);
    asm volatile("ldmatrix.sync.aligned.m8n8.x4.trans.shared.b16 {%0,%1,%2,%3}, [%4];"
                 : "=r"(r[0]), "=r"(r[1]), "=r"(r[2]), "=r"(r[3]) : "r"(a));
}
__device__ __forceinline__ void mma_bf16(float d[4], const uint32_t a[4], uint32_t b0, uint32_t b1) {
    asm volatile("mma.sync.aligned.m16n8k16.row.col.f32.bf16.bf16.f32 "
                 "{%0,%1,%2,%3}, {%4,%5,%6,%7}, {%8,%9}, {%0,%1,%2,%3};"
                 : "+f"(d[0]), "+f"(d[1]), "+f"(d[2]), "+f"(d[3])
                 : "r"(a[0]), "r"(a[1]), "r"(a[2]), "r"(a[3]), "r"(b0), "r"(b1));
}

__global__ __launch_bounds__(256, 1)
void fused_kernel(const float* __restrict__ x, const int* __restrict__ mod,
                  float* __restrict__ out)
{
    extern __shared__ __align__(16) __nv_bfloat16 smem[];
    __nv_bfloat16* sHh    = smem;
    __nv_bfloat16* sHl    = smem + HID * PITCH;
    __nv_bfloat16* AW     = smem + 2 * HID * PITCH;          // 34816
    __nv_bfloat16* sXh    = smem + 34816 + 2 * (2 * HID * PITCHW); // 71680
    __nv_bfloat16* sXl    = sXh + 64 * PITCH;
    float*         stageF = (float*)(smem + 89088);
    __nv_bfloat16* BW     = smem + 34816;

    const int tid  = threadIdx.x;
    const int warp = tid >> 5, lane = tid & 31;
    const int bimg = blockIdx.x / TILES;
    const int tile = blockIdx.x % TILES;
    const int p0   = tile * PIX_TILE;
    const int br   = (__ldg(&mod[bimg]) == 1) ? 0 : 1;
    const int wr = warp >> 1, wc = warp & 1;
    const int g  = lane >> 2, tg = lane & 3;
    const int l16 = lane & 15, lh = lane >> 4;

    const float* xb = x   + (size_t)bimg * C * HW;
    float*       ob = out + (size_t)bimg * C * HW;
    const __nv_bfloat16* w1h = g_w1h + br * HID * C;
    const __nv_bfloat16* w1l = g_w1l + br * HID * C;
    const __nv_bfloat16* w2h = g_w2h + br * C * HID;
    const __nv_bfloat16* w2l = g_w2l + br * C * HID;

    // --- cp.async issue helpers ---
    auto issue_X = [&](int i) {                 // X chunk i -> fp32 staging
        const int kc = i * 64;
        #pragma unroll
        for (int it = 0; it < 8; it++) {
            int idx = tid + it * 256;
            int row = idx >> 5;
            int pix = (idx & 31) << 2;
            int gp  = p0 + pix; if (gp > HW - 4) gp = HW - 4;   // clamp (masked at store)
            cp16(&stageF[row * PITCHF + pix], xb + (size_t)(kc + row) * HW + gp);
        }
    };
    auto issue_W1 = [&](int i) {                // W1 chunk i -> buffer i&1
        __nv_bfloat16* base = AW + (i & 1) * (2 * HID * PITCHW);
        const int kc = i * 64;
        #pragma unroll
        for (int it = 0; it < 8; it++) {
            int idx = tid + it * 256;
            int sp  = idx >> 10;                // 0=hi, 1=lo
            int r   = (idx >> 3) & 127;
            int c8  = (idx & 7) << 3;
            const __nv_bfloat16* s = (sp ? w1l : w1h) + r * C + kc + c8;
            cp16(base + sp * (HID * PITCHW) + r * PITCHW + c8, s);
        }
    };
    auto issue_W2 = [&](int j) {                // W2 chunk j -> buffer j&1
        __nv_bfloat16* base = BW + (j & 1) * (2 * HID * PITCH);
        const int cc = j * 128;
        #pragma unroll
        for (int it = 0; it < 16; it++) {
            int idx = tid + it * 256;
            int sp  = idx >> 11;
            int r   = (idx >> 4) & 127;
            int c8  = (idx & 15) << 3;
            const __nv_bfloat16* s = (sp ? w2l : w2h) + (cc + r) * HID + c8;
            cp16(base + sp * (HID * PITCH) + r * PITCH + c8, s);
        }
    };

    float acc[2][8][4];
    #pragma unroll
    for (int a = 0; a < 2; a++)
        #pragma unroll
        for (int b2 = 0; b2 < 8; b2++)
            #pragma unroll
            for (int c2 = 0; c2 < 4; c2++) acc[a][b2][c2] = 0.f;

    // prologue: chunk 0 in flight
    issue_X(0); issue_W1(0); CP_COMMIT();

    // ============ Phase A: D1 = W1 . X, K=512 in 8 chunks of 64 ============
    for (int i = 0; i < 8; i++) {
        CP_WAIT0();
        __syncthreads();                         // chunk i landed; mma i-1 done reading
        if (i < 7) issue_W1(i + 1);              // W buffer (i+1)&1 is free now
        // convert fp32 staging -> hi/lo bf16
        #pragma unroll
        for (int it = 0; it < 8; it++) {
            int idx = tid + it * 256;
            int row = idx >> 5;
            int pix = (idx & 31) << 2;
            float4 v = *(const float4*)&stageF[row * PITCHF + pix];
            __nv_bfloat16 h0,l0,h1,l1,h2,l2,h3,l3;
            split_bf16(v.x, h0, l0); split_bf16(v.y, h1, l1);
            split_bf16(v.z, h2, l2); split_bf16(v.w, h3, l3);
            *(__nv_bfloat162*)&sXh[row*PITCH + pix]     = __halves2bfloat162(h0, h1);
            *(__nv_bfloat162*)&sXh[row*PITCH + pix + 2] = __halves2bfloat162(h2, h3);
            *(__nv_bfloat162*)&sXl[row*PITCH + pix]     = __halves2bfloat162(l0, l1);
            *(__nv_bfloat162*)&sXl[row*PITCH + pix + 2] = __halves2bfloat162(l2, l3);
        }
        __syncthreads();                         // bf16 ready; staging free
        if (i < 7) issue_X(i + 1);
        CP_COMMIT();

        const __nv_bfloat16* bWh = AW + (i & 1) * (2 * HID * PITCHW);
        const __nv_bfloat16* bWl = bWh + HID * PITCHW;
        #pragma unroll
        for (int ks = 0; ks < 64; ks += 16) {
            uint32_t A[2][2][4];
            #pragma unroll
            for (int mf = 0; mf < 2; mf++) {
                const int ro = (32*wr + 16*mf + l16) * PITCHW + ks + 8*lh;
                ldsm4(A[0][mf], &bWh[ro]);
                ldsm4(A[1][mf], &bWl[ro]);
            }
            uint32_t Bt[2][4][4];
            #pragma unroll
            for (int nf = 0; nf < 4; nf++) {
                const int bo = (ks + l16) * PITCH + 64*wc + 16*nf + 8*lh;
                ldsm4t(Bt[0][nf], &sXh[bo]);
                ldsm4t(Bt[1][nf], &sXl[bo]);
            }
            #pragma unroll
            for (int mf = 0; mf < 2; mf++)
                #pragma unroll
                for (int nf = 0; nf < 4; nf++)
                    #pragma unroll
                    for (int hhalf = 0; hhalf < 2; hhalf++) {
                        float* d = acc[mf][nf*2 + hhalf];
                        mma_bf16(d, A[0][mf], Bt[0][nf][2*hhalf], Bt[0][nf][2*hhalf+1]);
                        mma_bf16(d, A[0][mf], Bt[1][nf][2*hhalf], Bt[1][nf][2*hhalf+1]);
                        mma_bf16(d, A[1][mf], Bt[0][nf][2*hhalf], Bt[0][nf][2*hhalf+1]);
                    }
        }
    }

    // prefetch W2 chunk 0 (buffer region overlaps W1/X — must be after all mma)
    __syncthreads();
    issue_W2(0); CP_COMMIT();

    // Epilogue A: BN + ReLU, split h -> sH
    #pragma unroll
    for (int mf = 0; mf < 2; mf++)
        #pragma unroll
        for (int rh = 0; rh < 2; rh++) {
            int row = 32*wr + 16*mf + 8*rh + g;
            float sc = g_ss[br*2*HID + row];
            float sh = g_ss[br*2*HID + HID + row];
            #pragma unroll
            for (int n8 = 0; n8 < 8; n8++) {
                int col = 64*wc + 8*n8 + 2*tg;
                float v0 = fmaxf(fmaf(acc[mf][n8][2*rh+0], sc, sh), 0.f);
                float v1 = fmaxf(fmaf(acc[mf][n8][2*rh+1], sc, sh), 0.f);
                __nv_bfloat16 h0,l0,h1,l1;
                split_bf16(v0, h0, l0);
                split_bf16(v1, h1, l1);
                *(__nv_bfloat162*)&sHh[row*PITCH + col] = __halves2bfloat162(h0, h1);
                *(__nv_bfloat162*)&sHl[row*PITCH + col] = __halves2bfloat162(l0, l1);
            }
        }

    // ============ Phase B: out = W2 . h, K=128, 4 chunks of 128 rows ============
    for (int j = 0; j < 4; j++) {
        CP_WAIT0();
        __syncthreads();                         // W2 chunk j landed; sH visible (j==0)
        if (j < 3) { issue_W2(j + 1); CP_COMMIT(); }

        #pragma unroll
        for (int a = 0; a < 2; a++)
            #pragma unroll
            for (int b2 = 0; b2 < 8; b2++)
                #pragma unroll
                for (int c2 = 0; c2 < 4; c2++) acc[a][b2][c2] = 0.f;

        const __nv_bfloat16* bWh = BW + (j & 1) * (2 * HID * PITCH);
        const __nv_bfloat16* bWl = bWh + HID * PITCH;
        #pragma unroll
        for (int ks = 0; ks < 128; ks += 16) {
            uint32_t A[2][2][4];
            #pragma unroll
            for (int mf = 0; mf < 2; mf++) {
                const int ro = (32*wr + 16*mf + l16) * PITCH + ks + 8*lh;
                ldsm4(A[0][mf], &bWh[ro]);
                ldsm4(A[1][mf], &bWl[ro]);
            }
            uint32_t Bt[2][4][4];
            #pragma unroll
            for (int nf = 0; nf < 4; nf++) {
                const int bo = (ks + l16) * PITCH + 64*wc + 16*nf + 8*lh;
                ldsm4t(Bt[0][nf], &sHh[bo]);
                ldsm4t(Bt[1][nf], &sHl[bo]);
            }
            #pragma unroll
            for (int mf = 0; mf < 2; mf++)
                #pragma unroll
                for (int nf = 0; nf < 4; nf++)
                    #pragma unroll
                    for (int hhalf = 0; hhalf < 2; hhalf++) {
                        float* d = acc[mf][nf*2 + hhalf];
                        mma_bf16(d, A[0][mf], Bt[0][nf][2*hhalf], Bt[0][nf][2*hhalf+1]);
                        mma_bf16(d, A[0][mf], Bt[1][nf][2*hhalf], Bt[1][nf][2*hhalf+1]);
                        mma_bf16(d, A[1][mf], Bt[0][nf][2*hhalf], Bt[0][nf][2*hhalf+1]);
                    }
        }
        const int cc = j * 128;
        #pragma unroll
        for (int mf = 0; mf < 2; mf++)
            #pragma unroll
            for (int rh = 0; rh < 2; rh++) {
                int row = 32*wr + 16*mf + 8*rh + g;
                #pragma unroll
                for (int n8 = 0; n8 < 8; n8++) {
                    int col = 64*wc + 8*n8 + 2*tg;
                    if (p0 + col < HW) {
                        float2 v = make_float2(acc[mf][n8][2*rh], acc[mf][n8][2*rh+1]);
                        *(float2*)&ob[(size_t)(cc + row) * HW + p0 + col] = v;
                    }
                }
            }
    }
}

extern "C" void kernel_launch(void* const* d_in, const int* in_sizes, int n_in,
                              void* d_out, int out_size)
{
    (void)in_sizes; (void)n_in; (void)out_size;
    const float* x   = (const float*)d_in[0];
    const int*   md  = (const int*)  d_in[1];
    const float* w1r = (const float*)d_in[2];
    const float* rmr = (const float*)d_in[3];
    const float* rvr = (const float*)d_in[4];
    const float* gr  = (const float*)d_in[5];
    const float* bbr = (const float*)d_in[6];
    const float* w2r = (const float*)d_in[7];
    const float* w1i = (const float*)d_in[8];
    const float* rmi = (const float*)d_in[9];
    const float* rvi = (const float*)d_in[10];
    const float* gi  = (const float*)d_in[11];
    const float* bbi = (const float*)d_in[12];
    const float* w2i = (const float*)d_in[13];
    float* out = (float*)d_out;

    cudaFuncSetAttribute(fused_kernel, cudaFuncAttributeMaxDynamicSharedMemorySize, SMEM_BYTES);

    prep_kernel<<<(HID * C + 255) / 256, 256>>>(w1r, w1i, w2r, w2i,
                                                rmr, rvr, gr, bbr,
                                                rmi, rvi, gi, bbi);
    fused_kernel<<<BATCH * TILES, 256, SMEM_BYTES>>>(x, md, out);
}

// round 6
// speedup vs baseline: 1.9071x; 1.9071x over previous
#include <cuda_runtime.h>
#include <cuda_fp16.h>
#include <cuda_bf16.h>
#include <cstdint>

#define BATCH 32
#define C 512
#define HW 3136
#define HID 128
#define PIX_TILE 128
#define TILES 25
#define KC 128              // Phase-A K chunk
#define PITCH 136           // fp16 pitch for 128-wide rows (272B)
#define EPS_BN 1e-5f

// smem: sH [128][PITCH] + sW [128][PITCH] + sX [128][PITCH], fp16
#define SMEM_BYTES (3 * HID * PITCH * 2)   // 104448 B -> 2 CTAs/SM

// fp16 weights (branch 0 = rgb, branch 1 = inf) + fused BN scale/shift
__device__ __align__(16) __half g_w1[2*HID*C];
__device__ __align__(16) __half g_w2[2*C*HID];
__device__ float g_ss[2*2*HID];

__global__ void prep_kernel(const float* __restrict__ w1r, const float* __restrict__ w1i,
                            const float* __restrict__ w2r, const float* __restrict__ w2i,
                            const float* __restrict__ rmr, const float* __restrict__ rvr,
                            const float* __restrict__ gr,  const float* __restrict__ bbr,
                            const float* __restrict__ rmi, const float* __restrict__ rvi,
                            const float* __restrict__ gi,  const float* __restrict__ bbi)
{
    int idx = blockIdx.x * blockDim.x + threadIdx.x;
    if (idx < HID * C) {
        g_w1[idx]           = __float2half_rn(w1r[idx]);
        g_w1[HID*C + idx]   = __float2half_rn(w1i[idx]);
        g_w2[idx]           = __float2half_rn(w2r[idx]);
        g_w2[C*HID + idx]   = __float2half_rn(w2i[idx]);
    }
    if (idx < HID) {
        float s0 = gr[idx] / sqrtf(rvr[idx] + EPS_BN);
        g_ss[idx]         = s0;
        g_ss[HID + idx]   = bbr[idx] - rmr[idx] * s0;
        float s1 = gi[idx] / sqrtf(rvi[idx] + EPS_BN);
        g_ss[2*HID + idx] = s1;
        g_ss[3*HID + idx] = bbi[idx] - rmi[idx] * s1;
    }
}

__device__ __forceinline__ void ldsm4(uint32_t r[4], const __half* p) {
    uint32_t a = (uint32_t)__cvta_generic_to_shared(p);
    asm volatile("ldmatrix.sync.aligned.m8n8.x4.shared.b16 {%0,%1,%2,%3}, [%4];"
                 : "=r"(r[0]), "=r"(r[1]), "=r"(r[2]), "=r"(r[3]) : "r"(a));
}
__device__ __forceinline__ void ldsm4t(uint32_t r[4], const __half* p) {
    uint32_t a = (uint32_t)__cvta_generic_to_shared(p);
    asm volatile("ldmatrix.sync.aligned.m8n8.x4.trans.shared.b16 {%0,%1,%2,%3}, [%4];"
                 : "=r"(r[0]), "=r"(r[1]), "=r"(r[2]), "=r"(r[3]) : "r"(a));
}
__device__ __forceinline__ void mma_fp16(float d[4], const uint32_t a[4], uint32_t b0, uint32_t b1) {
    asm volatile("mma.sync.aligned.m16n8k16.row.col.f32.f16.f16.f32 "
                 "{%0,%1,%2,%3}, {%4,%5,%6,%7}, {%8,%9}, {%0,%1,%2,%3};"
                 : "+f"(d[0]), "+f"(d[1]), "+f"(d[2]), "+f"(d[3])
                 : "r"(a[0]), "r"(a[1]), "r"(a[2]), "r"(a[3]), "r"(b0), "r"(b1));
}

__global__ __launch_bounds__(256, 2)
void fused_kernel(const float* __restrict__ x, const int* __restrict__ mod,
                  float* __restrict__ out)
{
    extern __shared__ __align__(16) __half smem[];
    __half* sH = smem;
    __half* sW = smem + HID * PITCH;
    __half* sX = smem + 2 * HID * PITCH;

    const int tid  = threadIdx.x;
    const int warp = tid >> 5, lane = tid & 31;
    const int bimg = blockIdx.x / TILES;
    const int tile = blockIdx.x % TILES;
    const int p0   = tile * PIX_TILE;
    const int br   = (__ldg(&mod[bimg]) == 1) ? 0 : 1;
    const int wr = warp >> 1, wc = warp & 1;      // 4x2 warps: 32 M-rows x 64 N-cols each
    const int g  = lane >> 2, tg = lane & 3;
    const int l16 = lane & 15, lh = lane >> 4;

    const float* xb = x   + (size_t)bimg * C * HW;
    float*       ob = out + (size_t)bimg * C * HW;
    const __half* w1 = g_w1 + br * HID * C;
    const __half* w2 = g_w2 + br * C * HID;

    float acc[2][8][4];
    #pragma unroll
    for (int a = 0; a < 2; a++)
        #pragma unroll
        for (int b2 = 0; b2 < 8; b2++)
            #pragma unroll
            for (int c2 = 0; c2 < 4; c2++) acc[a][b2][c2] = 0.f;

    // ============ Phase A: D1[128 hid][128 px] = W1 . X, K=512 in 4 chunks of 128 ============
    for (int i = 0; i < 4; i++) {
        const int kc = i * KC;
        __syncthreads();                           // prev mma done with sW/sX
        // W1 chunk: 128 rows x 128 cols fp16, uint4 = 8 halves, 8 per thread
        #pragma unroll
        for (int it = 0; it < 8; it++) {
            int idx = tid + it * 256;
            int r   = idx >> 4;
            int c8  = (idx & 15) << 3;
            *(uint4*)&sW[r * PITCH + c8] = *(const uint4*)&w1[r * C + kc + c8];
        }
        // X chunk: 128 ch x 128 px fp32 -> fp16 (two sub-batches of 8 float4/thread)
        #pragma unroll
        for (int sb = 0; sb < 2; sb++) {
            float4 v[8];
            #pragma unroll
            for (int it = 0; it < 8; it++) {
                int idx = tid + (sb * 8 + it) * 256;
                int row = idx >> 5;
                int pix = (idx & 31) << 2;
                int gp  = p0 + pix; if (gp > HW - 4) gp = HW - 4;  // clamp; tail cols never stored
                v[it] = *(const float4*)(xb + (size_t)(kc + row) * HW + gp);
            }
            #pragma unroll
            for (int it = 0; it < 8; it++) {
                int idx = tid + (sb * 8 + it) * 256;
                int row = idx >> 5;
                int pix = (idx & 31) << 2;
                *(__half2*)&sX[row * PITCH + pix]     = __floats2half2_rn(v[it].x, v[it].y);
                *(__half2*)&sX[row * PITCH + pix + 2] = __floats2half2_rn(v[it].z, v[it].w);
            }
        }
        __syncthreads();

        #pragma unroll
        for (int ks = 0; ks < KC; ks += 16) {
            uint32_t A[2][4];
            #pragma unroll
            for (int mf = 0; mf < 2; mf++)
                ldsm4(A[mf], &sW[(32*wr + 16*mf + l16) * PITCH + ks + 8*lh]);
            uint32_t Bt[4][4];
            #pragma unroll
            for (int nf = 0; nf < 4; nf++)
                ldsm4t(Bt[nf], &sX[(ks + l16) * PITCH + 64*wc + 16*nf + 8*lh]);
            #pragma unroll
            for (int mf = 0; mf < 2; mf++)
                #pragma unroll
                for (int nf = 0; nf < 4; nf++)
                    #pragma unroll
                    for (int hh = 0; hh < 2; hh++)
                        mma_fp16(acc[mf][nf*2 + hh], A[mf], Bt[nf][2*hh], Bt[nf][2*hh+1]);
        }
    }

    // Epilogue A: BN + ReLU -> fp16 h in sH
    __syncthreads();
    #pragma unroll
    for (int mf = 0; mf < 2; mf++)
        #pragma unroll
        for (int rh = 0; rh < 2; rh++) {
            int row = 32*wr + 16*mf + 8*rh + g;
            float sc = g_ss[br*2*HID + row];
            float sh = g_ss[br*2*HID + HID + row];
            #pragma unroll
            for (int n8 = 0; n8 < 8; n8++) {
                int col = 64*wc + 8*n8 + 2*tg;
                float v0 = fmaxf(fmaf(acc[mf][n8][2*rh+0], sc, sh), 0.f);
                float v1 = fmaxf(fmaf(acc[mf][n8][2*rh+1], sc, sh), 0.f);
                *(__half2*)&sH[row * PITCH + col] = __floats2half2_rn(v0, v1);
            }
        }

    // ============ Phase B: out[512 c][128 px] = W2 . h, K=128, 4 chunks of 128 channels ============
    for (int j = 0; j < 4; j++) {
        const int cc = j * 128;
        __syncthreads();                           // sH ready (j==0); prev mma done with sW
        #pragma unroll
        for (int it = 0; it < 8; it++) {
            int idx = tid + it * 256;
            int r   = idx >> 4;
            int c8  = (idx & 15) << 3;
            *(uint4*)&sW[r * PITCH + c8] = *(const uint4*)&w2[(cc + r) * HID + c8];
        }
        __syncthreads();

        #pragma unroll
        for (int a = 0; a < 2; a++)
            #pragma unroll
            for (int b2 = 0; b2 < 8; b2++)
                #pragma unroll
                for (int c2 = 0; c2 < 4; c2++) acc[a][b2][c2] = 0.f;

        #pragma unroll
        for (int ks = 0; ks < 128; ks += 16) {
            uint32_t A[2][4];
            #pragma unroll
            for (int mf = 0; mf < 2; mf++)
                ldsm4(A[mf], &sW[(32*wr + 16*mf + l16) * PITCH + ks + 8*lh]);
            uint32_t Bt[4][4];
            #pragma unroll
            for (int nf = 0; nf < 4; nf++)
                ldsm4t(Bt[nf], &sH[(ks + l16) * PITCH + 64*wc + 16*nf + 8*lh]);
            #pragma unroll
            for (int mf = 0; mf < 2; mf++)
                #pragma unroll
                for (int nf = 0; nf < 4; nf++)
                    #pragma unroll
                    for (int hh = 0; hh < 2; hh++)
                        mma_fp16(acc[mf][nf*2 + hh], A[mf], Bt[nf][2*hh], Bt[nf][2*hh+1]);
        }

        #pragma unroll
        for (int mf = 0; mf < 2; mf++)
            #pragma unroll
            for (int rh = 0; rh < 2; rh++) {
                int row = 32*wr + 16*mf + 8*rh + g;
                #pragma unroll
                for (int n8 = 0; n8 < 8; n8++) {
                    int col = 64*wc + 8*n8 + 2*tg;
                    if (p0 + col < HW) {
                        float2 v = make_float2(acc[mf][n8][2*rh], acc[mf][n8][2*rh+1]);
                        *(float2*)&ob[(size_t)(cc + row) * HW + p0 + col] = v;
                    }
                }
            }
    }
}

extern "C" void kernel_launch(void* const* d_in, const int* in_sizes, int n_in,
                              void* d_out, int out_size)
{
    (void)in_sizes; (void)n_in; (void)out_size;
    const float* x   = (const float*)d_in[0];
    const int*   md  = (const int*)  d_in[1];
    const float* w1r = (const float*)d_in[2];
    const float* rmr = (const float*)d_in[3];
    const float* rvr = (const float*)d_in[4];
    const float* gr  = (const float*)d_in[5];
    const float* bbr = (const float*)d_in[6];
    const float* w2r = (const float*)d_in[7];
    const float* w1i = (const float*)d_in[8];
    const float* rmi = (const float*)d_in[9];
    const float* rvi = (const float*)d_in[10];
    const float* gi  = (const float*)d_in[11];
    const float* bbi = (const float*)d_in[12];
    const float* w2i = (const float*)d_in[13];
    float* out = (float*)d_out;

    cudaFuncSetAttribute(fused_kernel, cudaFuncAttributeMaxDynamicSharedMemorySize, SMEM_BYTES);

    prep_kernel<<<(HID * C + 255) / 256, 256>>>(w1r, w1i, w2r, w2i,
                                                rmr, rvr, gr, bbr,
                                                rmi, rvi, gi, bbi);
    fused_kernel<<<BATCH * TILES, 256, SMEM_BYTES>>>(x, md, out);
}

// round 8
// speedup vs baseline: 1.9419x; 1.0183x over previous
#include <cuda_runtime.h>
#include <cuda_fp16.h>
#include <cstdint>

#define BATCH 32
#define C 512
#define HW 3136
#define HID 128
#define TILES 25
#define PITCH 136                 // halves per row (272B), conflict-free for ldsm
#define REGION (HID * PITCH * 2)  // 34816 B per 128-row tile region
#define EPS_BN 1e-5f
#define SMEM_BYTES (3 * REGION)   // 104448 -> 2 CTAs/SM

// Region roles:
//  R0: W chunk (phase A W1; phase B W2 ping even)
//  R1: X chunk even (phase A); W2 ping odd (phase B)
//  R2: X chunk odd (phase A); h tile (epilogue A onward)

__device__ __align__(16) __half g_w1[2*HID*C];
__device__ __align__(16) __half g_w2[2*C*HID];
__device__ float g_ss[2*2*HID];

__global__ void prep_kernel(const float* __restrict__ w1r, const float* __restrict__ w1i,
                            const float* __restrict__ w2r, const float* __restrict__ w2i,
                            const float* __restrict__ rmr, const float* __restrict__ rvr,
                            const float* __restrict__ gr,  const float* __restrict__ bbr,
                            const float* __restrict__ rmi, const float* __restrict__ rvi,
                            const float* __restrict__ gi,  const float* __restrict__ bbi)
{
    int idx = blockIdx.x * blockDim.x + threadIdx.x;
    if (idx < HID * C) {
        g_w1[idx]         = __float2half_rn(w1r[idx]);
        g_w1[HID*C + idx] = __float2half_rn(w1i[idx]);
        g_w2[idx]         = __float2half_rn(w2r[idx]);
        g_w2[C*HID + idx] = __float2half_rn(w2i[idx]);
    }
    if (idx < HID) {
        float s0 = gr[idx] / sqrtf(rvr[idx] + EPS_BN);
        g_ss[idx]         = s0;
        g_ss[HID + idx]   = bbr[idx] - rmr[idx] * s0;
        float s1 = gi[idx] / sqrtf(rvi[idx] + EPS_BN);
        g_ss[2*HID + idx] = s1;
        g_ss[3*HID + idx] = bbi[idx] - rmi[idx] * s1;
    }
}

__device__ __forceinline__ void cp16(uint32_t dst_smem, const void* src) {
    asm volatile("cp.async.cg.shared.global [%0], [%1], 16;\n" :: "r"(dst_smem), "l"(src));
}
#define CP_COMMIT() asm volatile("cp.async.commit_group;\n" ::)
#define CP_WAIT0()  asm volatile("cp.async.wait_group 0;\n" ::)

__device__ __forceinline__ void ldsm4a(uint32_t r[4], uint32_t a) {
    asm volatile("ldmatrix.sync.aligned.m8n8.x4.shared.b16 {%0,%1,%2,%3}, [%4];"
                 : "=r"(r[0]), "=r"(r[1]), "=r"(r[2]), "=r"(r[3]) : "r"(a));
}
__device__ __forceinline__ void ldsm4ta(uint32_t r[4], uint32_t a) {
    asm volatile("ldmatrix.sync.aligned.m8n8.x4.trans.shared.b16 {%0,%1,%2,%3}, [%4];"
                 : "=r"(r[0]), "=r"(r[1]), "=r"(r[2]), "=r"(r[3]) : "r"(a));
}
__device__ __forceinline__ void mma_fp16(float d[4], const uint32_t a[4], uint32_t b0, uint32_t b1) {
    asm volatile("mma.sync.aligned.m16n8k16.row.col.f32.f16.f16.f32 "
                 "{%0,%1,%2,%3}, {%4,%5,%6,%7}, {%8,%9}, {%0,%1,%2,%3};"
                 : "+f"(d[0]), "+f"(d[1]), "+f"(d[2]), "+f"(d[3])
                 : "r"(a[0]), "r"(a[1]), "r"(a[2]), "r"(a[3]), "r"(b0), "r"(b1));
}

// 128x128x128 GEMM tile with double-buffered fragments.
// aBase: per-warp A ldsm base; bBase: per-warp B (trans) ldsm base.
__device__ __forceinline__ void gemm128(uint32_t aBase, uint32_t bBase, float acc[2][8][4]) {
    uint32_t Af[2][2][4], Bf[2][4][4];
    ldsm4a(Af[0][0], aBase);
    ldsm4a(Af[0][1], aBase + 16 * PITCH * 2);
    #pragma unroll
    for (int nf = 0; nf < 4; nf++) ldsm4ta(Bf[0][nf], bBase + nf * 32);
    #pragma unroll
    for (int ks = 0; ks < 8; ks++) {
        const int cur = ks & 1, nxt = cur ^ 1;
        if (ks < 7) {
            uint32_t ao = aBase + (ks + 1) * 32;
            ldsm4a(Af[nxt][0], ao);
            ldsm4a(Af[nxt][1], ao + 16 * PITCH * 2);
            uint32_t bo = bBase + (ks + 1) * 16 * PITCH * 2;
            #pragma unroll
            for (int nf = 0; nf < 4; nf++) ldsm4ta(Bf[nxt][nf], bo + nf * 32);
        }
        #pragma unroll
        for (int mf = 0; mf < 2; mf++)
            #pragma unroll
            for (int nf = 0; nf < 4; nf++)
                #pragma unroll
                for (int hh = 0; hh < 2; hh++)
                    mma_fp16(acc[mf][nf*2 + hh], Af[cur][mf], Bf[cur][nf][2*hh], Bf[cur][nf][2*hh+1]);
    }
}

__global__ __launch_bounds__(256, 2)
void fused_kernel(const float* __restrict__ x, const int* __restrict__ mod,
                  float* __restrict__ out)
{
    extern __shared__ __align__(16) __half smem[];
    const uint32_t sb = (uint32_t)__cvta_generic_to_shared(smem);
    const uint32_t R0 = sb, R1 = sb + REGION, R2 = sb + 2 * REGION;
    __half* hR0 = smem;
    __half* hR1 = smem + HID * PITCH;
    __half* hR2 = smem + 2 * HID * PITCH;

    const int tid  = threadIdx.x;
    const int warp = tid >> 5, lane = tid & 31;
    const int bimg = blockIdx.x / TILES;
    const int tile = blockIdx.x % TILES;
    const int p0   = tile * 128;
    const int br   = (__ldg(&mod[bimg]) == 1) ? 0 : 1;
    const int wr = warp >> 1, wc = warp & 1;
    const int g  = lane >> 2, tg = lane & 3;
    const int l16 = lane & 15, lh = lane >> 4;

    const float* xb = x   + (size_t)bimg * C * HW;
    float*       ob = out + (size_t)bimg * C * HW;
    const __half* w1 = g_w1 + br * HID * C;
    const __half* w2 = g_w2 + br * C * HID;

    // per-warp ldsm base offsets (bytes)
    const uint32_t aOff = ((32*wr + l16) * PITCH + 8*lh) * 2;
    const uint32_t bOff = (l16 * PITCH + 64*wc + 8*lh) * 2;

    // ---- fill helpers ----
    auto fillW1 = [&](int i) {            // W1 chunk i -> R0 via cp.async
        const int kc = i * 128;
        #pragma unroll
        for (int t = 0; t < 8; t++) {
            int idx = tid + t * 256;
            int r = idx >> 4, c8 = (idx & 15) << 3;
            cp16(R0 + (r * PITCH + c8) * 2, w1 + r * C + kc + c8);
        }
    };
    auto fillW2 = [&](int j) {            // W2 chunk j -> R0/R1 ping via cp.async
        const uint32_t dst = (j & 1) ? R1 : R0;
        const int cc = j * 128;
        #pragma unroll
        for (int t = 0; t < 8; t++) {
            int idx = tid + t * 256;
            int r = idx >> 4, c8 = (idx & 15) << 3;
            cp16(dst + (r * PITCH + c8) * 2, w2 + (size_t)(cc + r) * HID + c8);
        }
    };
    auto fillX = [&](int i) {             // X chunk i (128 ch x 128 px) fp32->fp16
        __half* dst = (i & 1) ? hR2 : hR1;
        const int kc = i * 128;
        #pragma unroll
        for (int b4 = 0; b4 < 4; b4++) {
            float4 v[4];
            #pragma unroll
            for (int t = 0; t < 4; t++) {
                int idx = tid + (b4 * 4 + t) * 256;
                int row = idx >> 5;
                int pg  = (idx & 31) << 2;
                int gp  = p0 + pg; if (gp > HW - 4) gp = HW - 4;
                v[t] = *(const float4*)(xb + (size_t)(kc + row) * HW + gp);
            }
            #pragma unroll
            for (int t = 0; t < 4; t++) {
                int idx = tid + (b4 * 4 + t) * 256;
                int row = idx >> 5;
                int pg  = (idx & 31) << 2;
                *(__half2*)&dst[row * PITCH + pg]     = __floats2half2_rn(v[t].x, v[t].y);
                *(__half2*)&dst[row * PITCH + pg + 2] = __floats2half2_rn(v[t].z, v[t].w);
            }
        }
    };

    float acc[2][8][4];
    #pragma unroll
    for (int a = 0; a < 2; a++)
        #pragma unroll
        for (int b2 = 0; b2 < 8; b2++)
            #pragma unroll
            for (int c2 = 0; c2 < 4; c2++) acc[a][b2][c2] = 0.f;

    // ================= Phase A: D1 = W1 . X, K=512, 4 chunks =================
    fillW1(0); CP_COMMIT();
    fillX(0);
    CP_WAIT0(); __syncthreads();
    for (int i = 0; i < 4; i++) {
        gemm128(R0 + aOff, ((i & 1) ? R2 : R1) + bOff, acc);
        __syncthreads();                       // all warps done with R0 + bufX(i)
        if (i < 3) {
            fillW1(i + 1); CP_COMMIT();
            fillX(i + 1);
            CP_WAIT0(); __syncthreads();
        }
    }

    // transition: W2 chunk 0 -> R0 (free), epilogue A -> R2 (free)
    fillW2(0); CP_COMMIT();
    {
        #pragma unroll
        for (int mf = 0; mf < 2; mf++)
            #pragma unroll
            for (int rh = 0; rh < 2; rh++) {
                int row = 32*wr + 16*mf + 8*rh + g;
                float sc = g_ss[br*2*HID + row];
                float sh = g_ss[br*2*HID + HID + row];
                #pragma unroll
                for (int n8 = 0; n8 < 8; n8++) {
                    int col = 64*wc + 8*n8 + 2*tg;
                    float v0 = fmaxf(fmaf(acc[mf][n8][2*rh+0], sc, sh), 0.f);
                    float v1 = fmaxf(fmaf(acc[mf][n8][2*rh+1], sc, sh), 0.f);
                    *(__half2*)&hR2[row * PITCH + col] = __floats2half2_rn(v0, v1);
                }
            }
    }
    CP_WAIT0(); __syncthreads();               // h + W2 chunk 0 visible

    // ================= Phase B: out = W2 . h, K=128, 4 chunks =================
    for (int j = 0; j < 4; j++) {
        #pragma unroll
        for (int a = 0; a < 2; a++)
            #pragma unroll
            for (int b2 = 0; b2 < 8; b2++)
                #pragma unroll
                for (int c2 = 0; c2 < 4; c2++) acc[a][b2][c2] = 0.f;

        gemm128(((j & 1) ? R1 : R0) + aOff, R2 + bOff, acc);
        __syncthreads();                       // all warps done mma j -> buf (j+1)&1 free
        if (j < 3) { fillW2(j + 1); CP_COMMIT(); }   // overlaps stores below

        const int cc = j * 128;
        #pragma unroll
        for (int mf = 0; mf < 2; mf++)
            #pragma unroll
            for (int rh = 0; rh < 2; rh++) {
                int row = 32*wr + 16*mf + 8*rh + g;
                #pragma unroll
                for (int n8 = 0; n8 < 8; n8++) {
                    int col = 64*wc + 8*n8 + 2*tg;
                    if (p0 + col < HW) {
                        float2 v = make_float2(acc[mf][n8][2*rh], acc[mf][n8][2*rh+1]);
                        *(float2*)&ob[(size_t)(cc + row) * HW + p0 + col] = v;
                    }
                }
            }
        if (j < 3) { CP_WAIT0(); __syncthreads(); }
    }
}

extern "C" void kernel_launch(void* const* d_in, const int* in_sizes, int n_in,
                              void* d_out, int out_size)
{
    (void)in_sizes; (void)n_in; (void)out_size;
    const float* x   = (const float*)d_in[0];
    const int*   md  = (const int*)  d_in[1];
    const float* w1r = (const float*)d_in[2];
    const float* rmr = (const float*)d_in[3];
    const float* rvr = (const float*)d_in[4];
    const float* gr  = (const float*)d_in[5];
    const float* bbr = (const float*)d_in[6];
    const float* w2r = (const float*)d_in[7];
    const float* w1i = (const float*)d_in[8];
    const float* rmi = (const float*)d_in[9];
    const float* rvi = (const float*)d_in[10];
    const float* gi  = (const float*)d_in[11];
    const float* bbi = (const float*)d_in[12];
    const float* w2i = (const float*)d_in[13];
    float* out = (float*)d_out;

    cudaFuncSetAttribute(fused_kernel, cudaFuncAttributeMaxDynamicSharedMemorySize, SMEM_BYTES);

    prep_kernel<<<(HID * C + 255) / 256, 256>>>(w1r, w1i, w2r, w2i,
                                                rmr, rvr, gr, bbr,
                                                rmi, rvi, gi, bbi);
    fused_kernel<<<BATCH * TILES, 256, SMEM_BYTES>>>(x, md, out);
}

// round 9
// speedup vs baseline: 1.9635x; 1.0111x over previous
#include <cuda_runtime.h>
#include <cuda_fp16.h>
#include <cstdint>

#define BATCH 32
#define C 512
#define HW 3136
#define HID 128
#define TILES 25
#define EPS_BN 1e-5f

#define PA 72       // phase-A W pitch (halves): 144B rows, conflict-free ldsm
#define PB 136      // X / h / W2 pitch (halves): 272B rows

// smem regions (byte offsets from dynamic base)
#define OFF_W0 0
#define OFF_W1 18432
#define OFF_X0 36864
#define OFF_X1 54272
#define OFF_H  71680
#define SMEM_BYTES 106496    // 104 KB -> 2 CTAs/SM

__device__ __align__(16) __half g_w1[2*HID*C];
__device__ __align__(16) __half g_w2[2*C*HID];
__device__ float g_ss[2*2*HID];

__global__ void prep_kernel(const float* __restrict__ w1r, const float* __restrict__ w1i,
                            const float* __restrict__ w2r, const float* __restrict__ w2i,
                            const float* __restrict__ rmr, const float* __restrict__ rvr,
                            const float* __restrict__ gr,  const float* __restrict__ bbr,
                            const float* __restrict__ rmi, const float* __restrict__ rvi,
                            const float* __restrict__ gi,  const float* __restrict__ bbi)
{
    int idx = blockIdx.x * blockDim.x + threadIdx.x;
    if (idx < HID * C) {
        g_w1[idx]         = __float2half_rn(w1r[idx]);
        g_w1[HID*C + idx] = __float2half_rn(w1i[idx]);
        g_w2[idx]         = __float2half_rn(w2r[idx]);
        g_w2[C*HID + idx] = __float2half_rn(w2i[idx]);
    }
    if (idx < HID) {
        float s0 = gr[idx] / sqrtf(rvr[idx] + EPS_BN);
        g_ss[idx]         = s0;
        g_ss[HID + idx]   = bbr[idx] - rmr[idx] * s0;
        float s1 = gi[idx] / sqrtf(rvi[idx] + EPS_BN);
        g_ss[2*HID + idx] = s1;
        g_ss[3*HID + idx] = bbi[idx] - rmi[idx] * s1;
    }
}

__device__ __forceinline__ void cp16(uint32_t dst_smem, const void* src) {
    asm volatile("cp.async.cg.shared.global [%0], [%1], 16;\n" :: "r"(dst_smem), "l"(src));
}
#define CP_COMMIT() asm volatile("cp.async.commit_group;\n" ::)
#define CP_WAIT0()  asm volatile("cp.async.wait_group 0;\n" ::)

__device__ __forceinline__ void ldsm4a(uint32_t r[4], uint32_t a) {
    asm volatile("ldmatrix.sync.aligned.m8n8.x4.shared.b16 {%0,%1,%2,%3}, [%4];"
                 : "=r"(r[0]), "=r"(r[1]), "=r"(r[2]), "=r"(r[3]) : "r"(a));
}
__device__ __forceinline__ void ldsm4ta(uint32_t r[4], uint32_t a) {
    asm volatile("ldmatrix.sync.aligned.m8n8.x4.trans.shared.b16 {%0,%1,%2,%3}, [%4];"
                 : "=r"(r[0]), "=r"(r[1]), "=r"(r[2]), "=r"(r[3]) : "r"(a));
}
__device__ __forceinline__ void mma_fp16(float d[4], const uint32_t a[4], uint32_t b0, uint32_t b1) {
    asm volatile("mma.sync.aligned.m16n8k16.row.col.f32.f16.f16.f32 "
                 "{%0,%1,%2,%3}, {%4,%5,%6,%7}, {%8,%9}, {%0,%1,%2,%3};"
                 : "+f"(d[0]), "+f"(d[1]), "+f"(d[2]), "+f"(d[3])
                 : "r"(a[0]), "r"(a[1]), "r"(a[2]), "r"(a[3]), "r"(b0), "r"(b1));
}

__global__ __launch_bounds__(256, 2)
void fused_kernel(const float* __restrict__ x, const int* __restrict__ mod,
                  float* __restrict__ out)
{
    extern __shared__ __align__(16) __half smem[];
    const uint32_t sb = (uint32_t)__cvta_generic_to_shared(smem);
    __half* sH = smem + OFF_H / 2;

    const int tid  = threadIdx.x;
    const int warp = tid >> 5, lane = tid & 31;
    const int bimg = blockIdx.x / TILES;
    const int tile = blockIdx.x % TILES;
    const int p0   = tile * 128;
    const int br   = (__ldg(&mod[bimg]) == 1) ? 0 : 1;
    const int wr = warp >> 1, wc = warp & 1;      // phase-A grid 4x2
    const int wr2 = warp >> 2, wc2 = warp & 3;    // phase-B grid 2x4
    const int g  = lane >> 2, tg = lane & 3;
    const int l16 = lane & 15, lh = lane >> 4;

    const float* xb = x   + (size_t)bimg * C * HW;
    float*       ob = out + (size_t)bimg * C * HW;
    const __half* w1 = g_w1 + br * HID * C;
    const __half* w2 = g_w2 + br * C * HID;

    // ---------------- fill helpers ----------------
    auto cpW1 = [&](int i) {                      // W1 chunk [128 hid x 64 k] -> W(i&1)
        const uint32_t dst = sb + ((i & 1) ? OFF_W1 : OFF_W0);
        const int kc = i * 64;
        #pragma unroll
        for (int t = 0; t < 4; t++) {
            int idx = tid + t * 256;
            int r = idx >> 3, u = idx & 7;
            cp16(dst + (r * PA + u * 8) * 2, w1 + r * C + kc + u * 8);
        }
    };
    auto cpW2 = [&](int j) {                      // W2 chunk [64 ch x 128 k] -> W(j&1)
        const uint32_t dst = sb + ((j & 1) ? OFF_W1 : OFF_W0);
        const int cc = j * 64;
        #pragma unroll
        for (int t = 0; t < 4; t++) {
            int idx = tid + t * 256;
            int r = idx >> 4, u = idx & 15;
            cp16(dst + (r * PB + u * 8) * 2, w2 + (size_t)(cc + r) * HID + u * 8);
        }
    };
    float4 xv[8];
    auto ldgX = [&](int i) {                      // X chunk [64 ch x 128 px] -> regs
        const int kc = i * 64;
        #pragma unroll
        for (int t = 0; t < 8; t++) {
            int idx = tid + t * 256;
            int row = idx >> 5;
            int pg  = (idx & 31) << 2;
            int gp  = p0 + pg; if (gp > HW - 4) gp = HW - 4;
            xv[t] = *(const float4*)(xb + (size_t)(kc + row) * HW + gp);
        }
    };
    auto cvtstsX = [&](int buf) {                 // regs -> fp16 X(buf)
        __half* dst = smem + (buf ? OFF_X1 : OFF_X0) / 2;
        #pragma unroll
        for (int t = 0; t < 8; t++) {
            int idx = tid + t * 256;
            int row = idx >> 5;
            int pg  = (idx & 31) << 2;
            __half2 h0 = __floats2half2_rn(xv[t].x, xv[t].y);
            __half2 h1 = __floats2half2_rn(xv[t].z, xv[t].w);
            uint2 pk;
            pk.x = *reinterpret_cast<uint32_t*>(&h0);
            pk.y = *reinterpret_cast<uint32_t*>(&h1);
            *(uint2*)&dst[row * PB + pg] = pk;
        }
    };

    float acc[2][8][4];
    #pragma unroll
    for (int a = 0; a < 2; a++)
        #pragma unroll
        for (int b2 = 0; b2 < 8; b2++)
            #pragma unroll
            for (int c2 = 0; c2 < 4; c2++) acc[a][b2][c2] = 0.f;

    // ============ Phase A: D1[128 hid x 128 px] = W1 . X, K=512 in 8 chunks of 64 ============
    ldgX(0);
    cpW1(0); CP_COMMIT();
    cvtstsX(0);
    ldgX(1);
    CP_WAIT0(); __syncthreads();

    for (int i = 0; i < 8; i++) {
        if (i < 7) { cpW1(i + 1); CP_COMMIT(); }
        // gemm over chunk i: Kc=64, 4 ksteps
        {
            const uint32_t wb = sb + ((i & 1) ? OFF_W1 : OFF_W0);
            const uint32_t xbuf = sb + ((i & 1) ? OFF_X1 : OFF_X0);
            #pragma unroll
            for (int ks = 0; ks < 64; ks += 16) {
                uint32_t Af[2][4];
                #pragma unroll
                for (int mf = 0; mf < 2; mf++)
                    ldsm4a(Af[mf], wb + ((32*wr + 16*mf + l16) * PA + ks + 8*lh) * 2);
                #pragma unroll
                for (int nfh = 0; nfh < 2; nfh++) {
                    uint32_t B0[4], B1[4];
                    uint32_t base = xbuf + ((ks + l16) * PB + 64*wc + 32*nfh + 8*lh) * 2;
                    ldsm4ta(B0, base);
                    ldsm4ta(B1, base + 32);
                    #pragma unroll
                    for (int mf = 0; mf < 2; mf++) {
                        mma_fp16(acc[mf][nfh*4 + 0], Af[mf], B0[0], B0[1]);
                        mma_fp16(acc[mf][nfh*4 + 1], Af[mf], B0[2], B0[3]);
                        mma_fp16(acc[mf][nfh*4 + 2], Af[mf], B1[0], B1[1]);
                        mma_fp16(acc[mf][nfh*4 + 3], Af[mf], B1[2], B1[3]);
                    }
                }
            }
        }
        if (i < 7) {
            cvtstsX((i + 1) & 1);                 // X(i+1) regs -> other buffer
            if (i < 6) ldgX(i + 2);               // prefetch under next gemm
            CP_WAIT0();
        }
        __syncthreads();
    }

    // ---- transition: start W2(0) copy; epilogue A (BN+ReLU -> h) ----
    cpW2(0); CP_COMMIT();
    #pragma unroll
    for (int mf = 0; mf < 2; mf++)
        #pragma unroll
        for (int rh = 0; rh < 2; rh++) {
            int row = 32*wr + 16*mf + 8*rh + g;
            float sc = g_ss[br*2*HID + row];
            float sh = g_ss[br*2*HID + HID + row];
            #pragma unroll
            for (int n8 = 0; n8 < 8; n8++) {
                int col = 64*wc + 8*n8 + 2*tg;
                float v0 = fmaxf(fmaf(acc[mf][n8][2*rh+0], sc, sh), 0.f);
                float v1 = fmaxf(fmaf(acc[mf][n8][2*rh+1], sc, sh), 0.f);
                *(__half2*)&sH[row * PB + col] = __floats2half2_rn(v0, v1);
            }
        }
    CP_WAIT0(); __syncthreads();

    // ============ Phase B: out = W2 . h, 8 chunks of 64 channels, K=128 ============
    for (int j = 0; j < 8; j++) {
        if (j < 7) { cpW2(j + 1); CP_COMMIT(); }

        float ac[2][4][4];
        #pragma unroll
        for (int a = 0; a < 2; a++)
            #pragma unroll
            for (int b2 = 0; b2 < 4; b2++)
                #pragma unroll
                for (int c2 = 0; c2 < 4; c2++) ac[a][b2][c2] = 0.f;

        {
            const uint32_t wb = sb + ((j & 1) ? OFF_W1 : OFF_W0);
            const uint32_t hb = sb + OFF_H;
            #pragma unroll
            for (int ks = 0; ks < 128; ks += 16) {
                uint32_t Af[2][4];
                #pragma unroll
                for (int mf = 0; mf < 2; mf++)
                    ldsm4a(Af[mf], wb + ((32*wr2 + 16*mf + l16) * PB + ks + 8*lh) * 2);
                uint32_t Bf[2][4];
                #pragma unroll
                for (int nf = 0; nf < 2; nf++)
                    ldsm4ta(Bf[nf], hb + ((ks + l16) * PB + 32*wc2 + 16*nf + 8*lh) * 2);
                #pragma unroll
                for (int mf = 0; mf < 2; mf++)
                    #pragma unroll
                    for (int nf = 0; nf < 2; nf++) {
                        mma_fp16(ac[mf][nf*2 + 0], Af[mf], Bf[nf][0], Bf[nf][1]);
                        mma_fp16(ac[mf][nf*2 + 1], Af[mf], Bf[nf][2], Bf[nf][3]);
                    }
            }
        }

        // store chunk j: channels 64j + [0,64), 128 px (STG overlaps in-flight cp)
        const int cc = j * 64;
        #pragma unroll
        for (int mf = 0; mf < 2; mf++)
            #pragma unroll
            for (int rh = 0; rh < 2; rh++) {
                int row = 32*wr2 + 16*mf + 8*rh + g;
                #pragma unroll
                for (int n8 = 0; n8 < 4; n8++) {
                    int col = 32*wc2 + 8*n8 + 2*tg;
                    if (p0 + col < HW) {
                        float2 v = make_float2(ac[mf][n8][2*rh], ac[mf][n8][2*rh+1]);
                        *(float2*)&ob[(size_t)(cc + row) * HW + p0 + col] = v;
                    }
                }
            }
        if (j < 7) { CP_WAIT0(); __syncthreads(); }
    }
}

extern "C" void kernel_launch(void* const* d_in, const int* in_sizes, int n_in,
                              void* d_out, int out_size)
{
    (void)in_sizes; (void)n_in; (void)out_size;
    const float* x   = (const float*)d_in[0];
    const int*   md  = (const int*)  d_in[1];
    const float* w1r = (const float*)d_in[2];
    const float* rmr = (const float*)d_in[3];
    const float* rvr = (const float*)d_in[4];
    const float* gr  = (const float*)d_in[5];
    const float* bbr = (const float*)d_in[6];
    const float* w2r = (const float*)d_in[7];
    const float* w1i = (const float*)d_in[8];
    const float* rmi = (const float*)d_in[9];
    const float* rvi = (const float*)d_in[10];
    const float* gi  = (const float*)d_in[11];
    const float* bbi = (const float*)d_in[12];
    const float* w2i = (const float*)d_in[13];
    float* out = (float*)d_out;

    cudaFuncSetAttribute(fused_kernel, cudaFuncAttributeMaxDynamicSharedMemorySize, SMEM_BYTES);

    prep_kernel<<<(HID * C + 255) / 256, 256>>>(w1r, w1i, w2r, w2i,
                                                rmr, rvr, gr, bbr,
                                                rmi, rvi, gi, bbi);
    fused_kernel<<<BATCH * TILES, 256, SMEM_BYTES>>>(x, md, out);
}